// round 4
// baseline (speedup 1.0000x reference)
#include <cuda_runtime.h>

// Problem constants
#define Bq   8
#define Nn   5000
#define Ee   40000
#define Ff   64
#define FEe  16
#define FIL  96
#define DM   144   // 2F + FE
#define DU   160   // F + FILTERS
#define LN_EPS 1e-3f

// Scratch: per-node aggregated messages (B, N, FILTERS)
__device__ __align__(16) float g_agg[(size_t)Bq * Nn * FIL];

// ---------------- packed f32x2 helpers ----------------
__device__ __forceinline__ unsigned long long dup2(float x) {
    unsigned long long r;
    asm("mov.b64 %0, {%1, %1};" : "=l"(r) : "f"(x));
    return r;
}
__device__ __forceinline__ void fma2(unsigned long long& d,
                                     unsigned long long a,
                                     unsigned long long b) {
    asm("fma.rn.f32x2 %0, %1, %2, %0;" : "+l"(d) : "l"(a), "l"(b));
}
__device__ __forceinline__ void unpack2(unsigned long long v, float& lo, float& hi) {
    asm("mov.b64 {%0, %1}, %2;" : "=f"(lo), "=f"(hi) : "l"(v));
}
__device__ __forceinline__ void red4(float* addr, float4 v) {
    asm volatile("red.global.add.v4.f32 [%0], {%1,%2,%3,%4};"
                 :: "l"(addr), "f"(v.x), "f"(v.y), "f"(v.z), "f"(v.w) : "memory");
}

// ---------------- zero the aggregate buffer ----------------
__global__ void zero_agg_kernel() {
    const size_t n4 = (size_t)Bq * Nn * FIL / 4;  // 960000
    float4* p = (float4*)g_agg;
    for (size_t i = (size_t)blockIdx.x * blockDim.x + threadIdx.x; i < n4;
         i += (size_t)gridDim.x * blockDim.x)
        p[i] = make_float4(0.f, 0.f, 0.f, 0.f);
}

// ---------------- edge kernel ----------------
// Per block: 64 edges. GEMM (64x96, K=144) + relu + LayerNorm + store messages
// + vector-atomic segment-sum into g_agg by destination node.
// smem floats: Ws 13824 | As 9216 (overlaid by Ms 6144) | dst 64i | bm/gm/bt 3*96
#define E_WS   0
#define E_AS   13824
#define E_DST  23040
#define E_BM   23104
#define E_GM   23200
#define E_BT   23296
#define E_SMEM_FLOATS 23392
#define E_SMEM_BYTES (E_SMEM_FLOATS * 4)

__global__ void __launch_bounds__(256, 2) edge_kernel(
    const float*  __restrict__ nodes,
    const float*  __restrict__ ef,
    const int*    __restrict__ edges,
    const float*  __restrict__ Wm,
    const float*  __restrict__ bm,
    const float*  __restrict__ gm,
    const float*  __restrict__ bt,
    float*        __restrict__ msg_out)
{
    extern __shared__ float sm[];
    float* Ws   = sm + E_WS;
    float* As   = sm + E_AS;
    float* Ms   = sm + E_AS;   // overlay after GEMM
    int*   dsts = (int*)(sm + E_DST);
    float* bm_s = sm + E_BM;
    float* gm_s = sm + E_GM;
    float* bt_s = sm + E_BT;

    const int t = threadIdx.x;

    // stage Wm (144x96) into shared
    {
        const float4* w4 = (const float4*)Wm;
        float4* s4 = (float4*)Ws;
        for (int i = t; i < (DM * FIL) / 4; i += 256) s4[i] = w4[i];
        if (t < FIL) { bm_s[t] = bm[t]; gm_s[t] = gm[t]; bt_s[t] = bt[t]; }
    }

    // gather: 4 threads per edge build As[k][e] (k-major)
    const int le  = t >> 2;
    const int sub = t & 3;
    const int ge  = blockIdx.x * 64 + le;       // global edge id (< 320000)
    const int b   = ge / Ee;
    const int e   = ge % Ee;
    const int2 se = ((const int2*)edges)[(size_t)b * Ee + e];
    if (sub == 0) dsts[le] = se.y;
    {
        const float4* sr = (const float4*)(nodes + ((size_t)b * Nn + se.x) * Ff);
        const float4* dr = (const float4*)(nodes + ((size_t)b * Nn + se.y) * Ff);
        #pragma unroll
        for (int ii = 0; ii < 4; ii++) {
            float4 v = sr[sub * 4 + ii];
            int k = sub * 16 + ii * 4;
            As[(k + 0) * 64 + le] = v.x; As[(k + 1) * 64 + le] = v.y;
            As[(k + 2) * 64 + le] = v.z; As[(k + 3) * 64 + le] = v.w;
            v = dr[sub * 4 + ii];
            k += 64;
            As[(k + 0) * 64 + le] = v.x; As[(k + 1) * 64 + le] = v.y;
            As[(k + 2) * 64 + le] = v.z; As[(k + 3) * 64 + le] = v.w;
        }
        float4 v = ((const float4*)(ef + ((size_t)b * Ee + e) * FEe))[sub];
        int k = 128 + sub * 4;
        As[(k + 0) * 64 + le] = v.x; As[(k + 1) * 64 + le] = v.y;
        As[(k + 2) * 64 + le] = v.z; As[(k + 3) * 64 + le] = v.w;
    }
    __syncthreads();

    // GEMM: thread (tx,ty) -> edges ty*4..+3, filters tx*6..+5 (as 3 f32x2 pairs)
    const int tx = t & 15;
    const int ty = t >> 4;
    const float* Ap = As + ty * 4;
    const float* Wp = Ws + tx * 6;

    unsigned long long acc[4][3];
    #pragma unroll
    for (int i = 0; i < 4; i++)
        #pragma unroll
        for (int p = 0; p < 3; p++) acc[i][p] = 0ULL;

    #pragma unroll 4
    for (int k = 0; k < DM; k++) {
        float4 a = *(const float4*)(Ap + k * 64);
        unsigned long long a0 = dup2(a.x), a1 = dup2(a.y),
                           a2 = dup2(a.z), a3 = dup2(a.w);
        const float* wk = Wp + k * FIL;
        unsigned long long w0 = *(const unsigned long long*)(wk + 0);
        unsigned long long w1 = *(const unsigned long long*)(wk + 2);
        unsigned long long w2 = *(const unsigned long long*)(wk + 4);
        fma2(acc[0][0], a0, w0); fma2(acc[0][1], a0, w1); fma2(acc[0][2], a0, w2);
        fma2(acc[1][0], a1, w0); fma2(acc[1][1], a1, w1); fma2(acc[1][2], a1, w2);
        fma2(acc[2][0], a2, w0); fma2(acc[2][1], a2, w1); fma2(acc[2][2], a2, w2);
        fma2(acc[3][0], a3, w0); fma2(acc[3][1], a3, w1); fma2(acc[3][2], a3, w2);
    }

    // bias + relu + partial LN stats
    float r[4][6], s[4], q[4];
    #pragma unroll
    for (int ei = 0; ei < 4; ei++) {
        s[ei] = 0.f; q[ei] = 0.f;
        #pragma unroll
        for (int p = 0; p < 3; p++) {
            float lo, hi;
            unpack2(acc[ei][p], lo, hi);
            const int j = tx * 6 + 2 * p;
            lo = fmaxf(lo + bm_s[j], 0.f);
            hi = fmaxf(hi + bm_s[j + 1], 0.f);
            r[ei][2 * p] = lo; r[ei][2 * p + 1] = hi;
            s[ei] += lo + hi;  q[ei] += lo * lo + hi * hi;
        }
    }
    // reduce across the 16 lanes sharing ty (lanes [0..15] or [16..31])
    #pragma unroll
    for (int m = 1; m < 16; m <<= 1) {
        #pragma unroll
        for (int ei = 0; ei < 4; ei++) {
            s[ei] += __shfl_xor_sync(0xffffffffu, s[ei], m);
            q[ei] += __shfl_xor_sync(0xffffffffu, q[ei], m);
        }
    }

    __syncthreads();   // everyone done reading As before overlaying Ms

    #pragma unroll
    for (int ei = 0; ei < 4; ei++) {
        const float mean = s[ei] * (1.f / FIL);
        const float var  = q[ei] * (1.f / FIL) - mean * mean;
        const float rstd = rsqrtf(var + LN_EPS);
        const int el = ty * 4 + ei;
        #pragma unroll
        for (int jj = 0; jj < 6; jj++) {
            const int j = tx * 6 + jj;
            Ms[el * FIL + j] = (r[ei][jj] - mean) * rstd * gm_s[j] + bt_s[j];
        }
    }
    __syncthreads();

    // store messages (coalesced float4) + vector-atomic segment sum
    float4* mo = (float4*)(msg_out + (size_t)blockIdx.x * 64 * FIL);
    const float4* ms4 = (const float4*)Ms;
    #pragma unroll
    for (int rr = 0; rr < 6; rr++) {
        const int i = t + rr * 256;              // 0..1535
        float4 v = ms4[i];
        mo[i] = v;
        const int el = i / 24;                   // 24 float4 per edge
        const int j4 = (i % 24) * 4;
        float* ad = g_agg + ((size_t)b * Nn + dsts[el]) * FIL + j4;
        red4(ad, v);
    }
}

// ---------------- node kernel ----------------
// Per block: 64 nodes. GEMM (64x96, K=160) on [node(64) | agg(96)] + relu + LN.
#define U_WS   0
#define U_AS   15360
#define U_BM   25600
#define U_GM   25696
#define U_BT   25792
#define U_SMEM_FLOATS 25888
#define U_SMEM_BYTES (U_SMEM_FLOATS * 4)

__global__ void __launch_bounds__(256, 2) node_kernel(
    const float*  __restrict__ nodes,
    const float*  __restrict__ Wu,
    const float*  __restrict__ bu,
    const float*  __restrict__ gm,
    const float*  __restrict__ bt,
    float*        __restrict__ upd_out)
{
    extern __shared__ float sm[];
    float* Ws   = sm + U_WS;
    float* As   = sm + U_AS;
    float* Ms   = sm + U_AS;
    float* bm_s = sm + U_BM;
    float* gm_s = sm + U_GM;
    float* bt_s = sm + U_BT;

    const int t = threadIdx.x;

    {
        const float4* w4 = (const float4*)Wu;
        float4* s4 = (float4*)Ws;
        for (int i = t; i < (DU * FIL) / 4; i += 256) s4[i] = w4[i];
        if (t < FIL) { bm_s[t] = bu[t]; gm_s[t] = gm[t]; bt_s[t] = bt[t]; }
    }

    // gather: 4 threads per node
    const int ln  = t >> 2;
    const int sub = t & 3;
    const int gn  = blockIdx.x * 64 + ln;       // global node id (< 40000)
    const int b   = gn / Nn;
    const int n   = gn % Nn;
    {
        const float4* nr = (const float4*)(nodes + ((size_t)b * Nn + n) * Ff);
        #pragma unroll
        for (int ii = 0; ii < 4; ii++) {
            float4 v = nr[sub * 4 + ii];
            int k = sub * 16 + ii * 4;
            As[(k + 0) * 64 + ln] = v.x; As[(k + 1) * 64 + ln] = v.y;
            As[(k + 2) * 64 + ln] = v.z; As[(k + 3) * 64 + ln] = v.w;
        }
        const float4* ar = (const float4*)(g_agg + ((size_t)b * Nn + n) * FIL);
        #pragma unroll
        for (int ii = 0; ii < 6; ii++) {
            float4 v = ar[sub * 6 + ii];
            int k = Ff + sub * 24 + ii * 4;
            As[(k + 0) * 64 + ln] = v.x; As[(k + 1) * 64 + ln] = v.y;
            As[(k + 2) * 64 + ln] = v.z; As[(k + 3) * 64 + ln] = v.w;
        }
    }
    __syncthreads();

    const int tx = t & 15;
    const int ty = t >> 4;
    const float* Ap = As + ty * 4;
    const float* Wp = Ws + tx * 6;

    unsigned long long acc[4][3];
    #pragma unroll
    for (int i = 0; i < 4; i++)
        #pragma unroll
        for (int p = 0; p < 3; p++) acc[i][p] = 0ULL;

    #pragma unroll 4
    for (int k = 0; k < DU; k++) {
        float4 a = *(const float4*)(Ap + k * 64);
        unsigned long long a0 = dup2(a.x), a1 = dup2(a.y),
                           a2 = dup2(a.z), a3 = dup2(a.w);
        const float* wk = Wp + k * FIL;
        unsigned long long w0 = *(const unsigned long long*)(wk + 0);
        unsigned long long w1 = *(const unsigned long long*)(wk + 2);
        unsigned long long w2 = *(const unsigned long long*)(wk + 4);
        fma2(acc[0][0], a0, w0); fma2(acc[0][1], a0, w1); fma2(acc[0][2], a0, w2);
        fma2(acc[1][0], a1, w0); fma2(acc[1][1], a1, w1); fma2(acc[1][2], a1, w2);
        fma2(acc[2][0], a2, w0); fma2(acc[2][1], a2, w1); fma2(acc[2][2], a2, w2);
        fma2(acc[3][0], a3, w0); fma2(acc[3][1], a3, w1); fma2(acc[3][2], a3, w2);
    }

    float r[4][6], s[4], q[4];
    #pragma unroll
    for (int ei = 0; ei < 4; ei++) {
        s[ei] = 0.f; q[ei] = 0.f;
        #pragma unroll
        for (int p = 0; p < 3; p++) {
            float lo, hi;
            unpack2(acc[ei][p], lo, hi);
            const int j = tx * 6 + 2 * p;
            lo = fmaxf(lo + bm_s[j], 0.f);
            hi = fmaxf(hi + bm_s[j + 1], 0.f);
            r[ei][2 * p] = lo; r[ei][2 * p + 1] = hi;
            s[ei] += lo + hi;  q[ei] += lo * lo + hi * hi;
        }
    }
    #pragma unroll
    for (int m = 1; m < 16; m <<= 1) {
        #pragma unroll
        for (int ei = 0; ei < 4; ei++) {
            s[ei] += __shfl_xor_sync(0xffffffffu, s[ei], m);
            q[ei] += __shfl_xor_sync(0xffffffffu, q[ei], m);
        }
    }

    __syncthreads();

    #pragma unroll
    for (int ei = 0; ei < 4; ei++) {
        const float mean = s[ei] * (1.f / FIL);
        const float var  = q[ei] * (1.f / FIL) - mean * mean;
        const float rstd = rsqrtf(var + LN_EPS);
        const int el = ty * 4 + ei;
        #pragma unroll
        for (int jj = 0; jj < 6; jj++) {
            const int j = tx * 6 + jj;
            Ms[el * FIL + j] = (r[ei][jj] - mean) * rstd * gm_s[j] + bt_s[j];
        }
    }
    __syncthreads();

    float4* uo = (float4*)(upd_out + (size_t)blockIdx.x * 64 * FIL);
    const float4* ms4 = (const float4*)Ms;
    #pragma unroll
    for (int rr = 0; rr < 6; rr++) {
        const int i = t + rr * 256;
        uo[i] = ms4[i];
    }
}

// ---------------- launch ----------------
extern "C" void kernel_launch(void* const* d_in, const int* in_sizes, int n_in,
                              void* d_out, int out_size) {
    const float* nodes = (const float*)d_in[0];
    const float* ef    = (const float*)d_in[1];
    const int*   edges = (const int*)  d_in[2];
    const float* Wm    = (const float*)d_in[3];
    const float* bm    = (const float*)d_in[4];
    const float* gm_m  = (const float*)d_in[5];
    const float* bt_m  = (const float*)d_in[6];
    const float* Wu    = (const float*)d_in[7];
    const float* bu    = (const float*)d_in[8];
    const float* gm_u  = (const float*)d_in[9];
    const float* bt_u  = (const float*)d_in[10];

    float* out = (float*)d_out;
    float* upd = out;                                  // (B, N, FILTERS)
    float* msg = out + (size_t)Bq * Nn * FIL;          // (B, E, FILTERS)

    cudaFuncSetAttribute(edge_kernel, cudaFuncAttributeMaxDynamicSharedMemorySize,
                         E_SMEM_BYTES);
    cudaFuncSetAttribute(node_kernel, cudaFuncAttributeMaxDynamicSharedMemorySize,
                         U_SMEM_BYTES);

    zero_agg_kernel<<<1875, 512>>>();
    edge_kernel<<<(Bq * Ee) / 64, 256, E_SMEM_BYTES>>>(
        nodes, ef, edges, Wm, bm, gm_m, bt_m, msg);
    node_kernel<<<(Bq * Nn) / 64, 256, U_SMEM_BYTES>>>(
        nodes, Wu, bu, gm_u, bt_u, upd);
}

// round 5
// speedup vs baseline: 1.0010x; 1.0010x over previous
#include <cuda_runtime.h>

// Problem constants
#define Bq   8
#define Nn   5000
#define Ee   40000
#define Ff   64
#define FEe  16
#define FIL  96
#define DM   144   // 2F + FE
#define DU   160   // F + FILTERS
#define LN_EPS 1e-3f

// Scratch: per-node aggregated messages (B, N, FILTERS)
__device__ __align__(16) float g_agg[(size_t)Bq * Nn * FIL];

// ---------------- packed f32x2 helpers ----------------
__device__ __forceinline__ unsigned long long dup2(float x) {
    unsigned long long r;
    asm("mov.b64 %0, {%1, %1};" : "=l"(r) : "f"(x));
    return r;
}
__device__ __forceinline__ void fma2(unsigned long long& d,
                                     unsigned long long a,
                                     unsigned long long b) {
    asm("fma.rn.f32x2 %0, %1, %2, %0;" : "+l"(d) : "l"(a), "l"(b));
}
__device__ __forceinline__ void unpack2(unsigned long long v, float& lo, float& hi) {
    asm("mov.b64 {%0, %1}, %2;" : "=f"(lo), "=f"(hi) : "l"(v));
}
__device__ __forceinline__ void red4(float* addr, float4 v) {
    asm volatile("red.global.add.v4.f32 [%0], {%1,%2,%3,%4};"
                 :: "l"(addr), "f"(v.x), "f"(v.y), "f"(v.z), "f"(v.w) : "memory");
}

// ---------------- zero the aggregate buffer ----------------
__global__ void zero_agg_kernel() {
    const size_t n4 = (size_t)Bq * Nn * FIL / 4;  // 960000
    float4* p = (float4*)g_agg;
    for (size_t i = (size_t)blockIdx.x * blockDim.x + threadIdx.x; i < n4;
         i += (size_t)gridDim.x * blockDim.x)
        p[i] = make_float4(0.f, 0.f, 0.f, 0.f);
}

// ---------------- edge kernel ----------------
// Per block: 64 edges. GEMM (64x96, K=144) + relu + LayerNorm + store messages
// + vector-atomic segment-sum into g_agg by destination node.
// smem floats: Ws 13824 | As 9216 (overlaid by Ms 6144) | dst 64i | bm/gm/bt 3*96
#define E_WS   0
#define E_AS   13824
#define E_DST  23040
#define E_BM   23104
#define E_GM   23200
#define E_BT   23296
#define E_SMEM_FLOATS 23392
#define E_SMEM_BYTES (E_SMEM_FLOATS * 4)

__global__ void __launch_bounds__(256, 2) edge_kernel(
    const float*  __restrict__ nodes,
    const float*  __restrict__ ef,
    const int*    __restrict__ edges,
    const float*  __restrict__ Wm,
    const float*  __restrict__ bm,
    const float*  __restrict__ gm,
    const float*  __restrict__ bt,
    float*        __restrict__ msg_out)
{
    extern __shared__ float sm[];
    float* Ws   = sm + E_WS;
    float* As   = sm + E_AS;
    float* Ms   = sm + E_AS;   // overlay after GEMM
    int*   dsts = (int*)(sm + E_DST);
    float* bm_s = sm + E_BM;
    float* gm_s = sm + E_GM;
    float* bt_s = sm + E_BT;

    const int t = threadIdx.x;

    // stage Wm (144x96) into shared
    {
        const float4* w4 = (const float4*)Wm;
        float4* s4 = (float4*)Ws;
        for (int i = t; i < (DM * FIL) / 4; i += 256) s4[i] = w4[i];
        if (t < FIL) { bm_s[t] = bm[t]; gm_s[t] = gm[t]; bt_s[t] = bt[t]; }
    }

    // gather: 4 threads per edge build As[k][e] (k-major)
    const int le  = t >> 2;
    const int sub = t & 3;
    const int ge  = blockIdx.x * 64 + le;       // global edge id (< 320000)
    const int b   = ge / Ee;
    const int e   = ge % Ee;
    const int2 se = ((const int2*)edges)[(size_t)b * Ee + e];
    if (sub == 0) dsts[le] = se.y;
    {
        const float4* sr = (const float4*)(nodes + ((size_t)b * Nn + se.x) * Ff);
        const float4* dr = (const float4*)(nodes + ((size_t)b * Nn + se.y) * Ff);
        #pragma unroll
        for (int ii = 0; ii < 4; ii++) {
            float4 v = sr[sub * 4 + ii];
            int k = sub * 16 + ii * 4;
            As[(k + 0) * 64 + le] = v.x; As[(k + 1) * 64 + le] = v.y;
            As[(k + 2) * 64 + le] = v.z; As[(k + 3) * 64 + le] = v.w;
            v = dr[sub * 4 + ii];
            k += 64;
            As[(k + 0) * 64 + le] = v.x; As[(k + 1) * 64 + le] = v.y;
            As[(k + 2) * 64 + le] = v.z; As[(k + 3) * 64 + le] = v.w;
        }
        float4 v = ((const float4*)(ef + ((size_t)b * Ee + e) * FEe))[sub];
        int k = 128 + sub * 4;
        As[(k + 0) * 64 + le] = v.x; As[(k + 1) * 64 + le] = v.y;
        As[(k + 2) * 64 + le] = v.z; As[(k + 3) * 64 + le] = v.w;
    }
    __syncthreads();

    // GEMM: thread (tx,ty) -> edges ty*4..+3, filters tx*6..+5 (as 3 f32x2 pairs)
    const int tx = t & 15;
    const int ty = t >> 4;
    const float* Ap = As + ty * 4;
    const float* Wp = Ws + tx * 6;

    unsigned long long acc[4][3];
    #pragma unroll
    for (int i = 0; i < 4; i++)
        #pragma unroll
        for (int p = 0; p < 3; p++) acc[i][p] = 0ULL;

    #pragma unroll 4
    for (int k = 0; k < DM; k++) {
        float4 a = *(const float4*)(Ap + k * 64);
        unsigned long long a0 = dup2(a.x), a1 = dup2(a.y),
                           a2 = dup2(a.z), a3 = dup2(a.w);
        const float* wk = Wp + k * FIL;
        unsigned long long w0 = *(const unsigned long long*)(wk + 0);
        unsigned long long w1 = *(const unsigned long long*)(wk + 2);
        unsigned long long w2 = *(const unsigned long long*)(wk + 4);
        fma2(acc[0][0], a0, w0); fma2(acc[0][1], a0, w1); fma2(acc[0][2], a0, w2);
        fma2(acc[1][0], a1, w0); fma2(acc[1][1], a1, w1); fma2(acc[1][2], a1, w2);
        fma2(acc[2][0], a2, w0); fma2(acc[2][1], a2, w1); fma2(acc[2][2], a2, w2);
        fma2(acc[3][0], a3, w0); fma2(acc[3][1], a3, w1); fma2(acc[3][2], a3, w2);
    }

    // bias + relu + partial LN stats
    float r[4][6], s[4], q[4];
    #pragma unroll
    for (int ei = 0; ei < 4; ei++) {
        s[ei] = 0.f; q[ei] = 0.f;
        #pragma unroll
        for (int p = 0; p < 3; p++) {
            float lo, hi;
            unpack2(acc[ei][p], lo, hi);
            const int j = tx * 6 + 2 * p;
            lo = fmaxf(lo + bm_s[j], 0.f);
            hi = fmaxf(hi + bm_s[j + 1], 0.f);
            r[ei][2 * p] = lo; r[ei][2 * p + 1] = hi;
            s[ei] += lo + hi;  q[ei] += lo * lo + hi * hi;
        }
    }
    // reduce across the 16 lanes sharing ty (lanes [0..15] or [16..31])
    #pragma unroll
    for (int m = 1; m < 16; m <<= 1) {
        #pragma unroll
        for (int ei = 0; ei < 4; ei++) {
            s[ei] += __shfl_xor_sync(0xffffffffu, s[ei], m);
            q[ei] += __shfl_xor_sync(0xffffffffu, q[ei], m);
        }
    }

    __syncthreads();   // everyone done reading As before overlaying Ms

    #pragma unroll
    for (int ei = 0; ei < 4; ei++) {
        const float mean = s[ei] * (1.f / FIL);
        const float var  = q[ei] * (1.f / FIL) - mean * mean;
        const float rstd = rsqrtf(var + LN_EPS);
        const int el = ty * 4 + ei;
        #pragma unroll
        for (int jj = 0; jj < 6; jj++) {
            const int j = tx * 6 + jj;
            Ms[el * FIL + j] = (r[ei][jj] - mean) * rstd * gm_s[j] + bt_s[j];
        }
    }
    __syncthreads();

    // store messages (coalesced float4) + vector-atomic segment sum
    float4* mo = (float4*)(msg_out + (size_t)blockIdx.x * 64 * FIL);
    const float4* ms4 = (const float4*)Ms;
    #pragma unroll
    for (int rr = 0; rr < 6; rr++) {
        const int i = t + rr * 256;              // 0..1535
        float4 v = ms4[i];
        mo[i] = v;
        const int el = i / 24;                   // 24 float4 per edge
        const int j4 = (i % 24) * 4;
        float* ad = g_agg + ((size_t)b * Nn + dsts[el]) * FIL + j4;
        red4(ad, v);
    }
}

// ---------------- node kernel ----------------
// Per block: 64 nodes. GEMM (64x96, K=160) on [node(64) | agg(96)] + relu + LN.
#define U_WS   0
#define U_AS   15360
#define U_BM   25600
#define U_GM   25696
#define U_BT   25792
#define U_SMEM_FLOATS 25888
#define U_SMEM_BYTES (U_SMEM_FLOATS * 4)

__global__ void __launch_bounds__(256, 2) node_kernel(
    const float*  __restrict__ nodes,
    const float*  __restrict__ Wu,
    const float*  __restrict__ bu,
    const float*  __restrict__ gm,
    const float*  __restrict__ bt,
    float*        __restrict__ upd_out)
{
    extern __shared__ float sm[];
    float* Ws   = sm + U_WS;
    float* As   = sm + U_AS;
    float* Ms   = sm + U_AS;
    float* bm_s = sm + U_BM;
    float* gm_s = sm + U_GM;
    float* bt_s = sm + U_BT;

    const int t = threadIdx.x;

    {
        const float4* w4 = (const float4*)Wu;
        float4* s4 = (float4*)Ws;
        for (int i = t; i < (DU * FIL) / 4; i += 256) s4[i] = w4[i];
        if (t < FIL) { bm_s[t] = bu[t]; gm_s[t] = gm[t]; bt_s[t] = bt[t]; }
    }

    // gather: 4 threads per node
    const int ln  = t >> 2;
    const int sub = t & 3;
    const int gn  = blockIdx.x * 64 + ln;       // global node id (< 40000)
    const int b   = gn / Nn;
    const int n   = gn % Nn;
    {
        const float4* nr = (const float4*)(nodes + ((size_t)b * Nn + n) * Ff);
        #pragma unroll
        for (int ii = 0; ii < 4; ii++) {
            float4 v = nr[sub * 4 + ii];
            int k = sub * 16 + ii * 4;
            As[(k + 0) * 64 + ln] = v.x; As[(k + 1) * 64 + ln] = v.y;
            As[(k + 2) * 64 + ln] = v.z; As[(k + 3) * 64 + ln] = v.w;
        }
        const float4* ar = (const float4*)(g_agg + ((size_t)b * Nn + n) * FIL);
        #pragma unroll
        for (int ii = 0; ii < 6; ii++) {
            float4 v = ar[sub * 6 + ii];
            int k = Ff + sub * 24 + ii * 4;
            As[(k + 0) * 64 + ln] = v.x; As[(k + 1) * 64 + ln] = v.y;
            As[(k + 2) * 64 + ln] = v.z; As[(k + 3) * 64 + ln] = v.w;
        }
    }
    __syncthreads();

    const int tx = t & 15;
    const int ty = t >> 4;
    const float* Ap = As + ty * 4;
    const float* Wp = Ws + tx * 6;

    unsigned long long acc[4][3];
    #pragma unroll
    for (int i = 0; i < 4; i++)
        #pragma unroll
        for (int p = 0; p < 3; p++) acc[i][p] = 0ULL;

    #pragma unroll 4
    for (int k = 0; k < DU; k++) {
        float4 a = *(const float4*)(Ap + k * 64);
        unsigned long long a0 = dup2(a.x), a1 = dup2(a.y),
                           a2 = dup2(a.z), a3 = dup2(a.w);
        const float* wk = Wp + k * FIL;
        unsigned long long w0 = *(const unsigned long long*)(wk + 0);
        unsigned long long w1 = *(const unsigned long long*)(wk + 2);
        unsigned long long w2 = *(const unsigned long long*)(wk + 4);
        fma2(acc[0][0], a0, w0); fma2(acc[0][1], a0, w1); fma2(acc[0][2], a0, w2);
        fma2(acc[1][0], a1, w0); fma2(acc[1][1], a1, w1); fma2(acc[1][2], a1, w2);
        fma2(acc[2][0], a2, w0); fma2(acc[2][1], a2, w1); fma2(acc[2][2], a2, w2);
        fma2(acc[3][0], a3, w0); fma2(acc[3][1], a3, w1); fma2(acc[3][2], a3, w2);
    }

    float r[4][6], s[4], q[4];
    #pragma unroll
    for (int ei = 0; ei < 4; ei++) {
        s[ei] = 0.f; q[ei] = 0.f;
        #pragma unroll
        for (int p = 0; p < 3; p++) {
            float lo, hi;
            unpack2(acc[ei][p], lo, hi);
            const int j = tx * 6 + 2 * p;
            lo = fmaxf(lo + bm_s[j], 0.f);
            hi = fmaxf(hi + bm_s[j + 1], 0.f);
            r[ei][2 * p] = lo; r[ei][2 * p + 1] = hi;
            s[ei] += lo + hi;  q[ei] += lo * lo + hi * hi;
        }
    }
    #pragma unroll
    for (int m = 1; m < 16; m <<= 1) {
        #pragma unroll
        for (int ei = 0; ei < 4; ei++) {
            s[ei] += __shfl_xor_sync(0xffffffffu, s[ei], m);
            q[ei] += __shfl_xor_sync(0xffffffffu, q[ei], m);
        }
    }

    __syncthreads();

    #pragma unroll
    for (int ei = 0; ei < 4; ei++) {
        const float mean = s[ei] * (1.f / FIL);
        const float var  = q[ei] * (1.f / FIL) - mean * mean;
        const float rstd = rsqrtf(var + LN_EPS);
        const int el = ty * 4 + ei;
        #pragma unroll
        for (int jj = 0; jj < 6; jj++) {
            const int j = tx * 6 + jj;
            Ms[el * FIL + j] = (r[ei][jj] - mean) * rstd * gm_s[j] + bt_s[j];
        }
    }
    __syncthreads();

    float4* uo = (float4*)(upd_out + (size_t)blockIdx.x * 64 * FIL);
    const float4* ms4 = (const float4*)Ms;
    #pragma unroll
    for (int rr = 0; rr < 6; rr++) {
        const int i = t + rr * 256;
        uo[i] = ms4[i];
    }
}

// ---------------- launch ----------------
extern "C" void kernel_launch(void* const* d_in, const int* in_sizes, int n_in,
                              void* d_out, int out_size) {
    const float* nodes = (const float*)d_in[0];
    const float* ef    = (const float*)d_in[1];
    const int*   edges = (const int*)  d_in[2];
    const float* Wm    = (const float*)d_in[3];
    const float* bm    = (const float*)d_in[4];
    const float* gm_m  = (const float*)d_in[5];
    const float* bt_m  = (const float*)d_in[6];
    const float* Wu    = (const float*)d_in[7];
    const float* bu    = (const float*)d_in[8];
    const float* gm_u  = (const float*)d_in[9];
    const float* bt_u  = (const float*)d_in[10];

    float* out = (float*)d_out;
    float* upd = out;                                  // (B, N, FILTERS)
    float* msg = out + (size_t)Bq * Nn * FIL;          // (B, E, FILTERS)

    cudaFuncSetAttribute(edge_kernel, cudaFuncAttributeMaxDynamicSharedMemorySize,
                         E_SMEM_BYTES);
    cudaFuncSetAttribute(node_kernel, cudaFuncAttributeMaxDynamicSharedMemorySize,
                         U_SMEM_BYTES);

    zero_agg_kernel<<<1875, 512>>>();
    edge_kernel<<<(Bq * Ee) / 64, 256, E_SMEM_BYTES>>>(
        nodes, ef, edges, Wm, bm, gm_m, bt_m, msg);
    node_kernel<<<(Bq * Nn) / 64, 256, U_SMEM_BYTES>>>(
        nodes, Wu, bu, gm_u, bt_u, upd);
}

// round 7
// speedup vs baseline: 1.5896x; 1.5880x over previous
#include <cuda_runtime.h>
#include <cstdint>

#define Bq   8
#define Nn   5000
#define Ee   40000
#define Ff   64
#define FEe  16
#define FIL  96
#define DM   144
#define DU   160
#define LN_EPS 1e-3f

__device__ __align__(16) float g_agg[(size_t)Bq * Nn * FIL];

// ---------------- helpers ----------------
__device__ __forceinline__ void red4(float* addr, float4 v) {
    asm volatile("red.global.add.v4.f32 [%0], {%1,%2,%3,%4};"
                 :: "l"(addr), "f"(v.x), "f"(v.y), "f"(v.z), "f"(v.w) : "memory");
}

// split (x,y) fp32 pair into bf16x2 hi + bf16x2 lo (lo = residual)
__device__ __forceinline__ uint32_t split_pair(float x, float y, uint32_t& lo2) {
    uint32_t h;
    asm("cvt.rn.bf16x2.f32 %0, %1, %2;" : "=r"(h) : "f"(y), "f"(x));
    float hx = __uint_as_float(h << 16);
    float hy = __uint_as_float(h & 0xffff0000u);
    float rx = x - hx, ry = y - hy;
    asm("cvt.rn.bf16x2.f32 %0, %1, %2;" : "=r"(lo2) : "f"(ry), "f"(rx));
    return h;
}

__device__ __forceinline__ void mma_bf16(float* c, const uint32_t* a,
                                         uint32_t b0, uint32_t b1) {
    asm volatile(
        "mma.sync.aligned.m16n8k16.row.col.f32.bf16.bf16.f32 "
        "{%0,%1,%2,%3}, {%4,%5,%6,%7}, {%8,%9}, {%0,%1,%2,%3};"
        : "+f"(c[0]), "+f"(c[1]), "+f"(c[2]), "+f"(c[3])
        : "r"(a[0]), "r"(a[1]), "r"(a[2]), "r"(a[3]), "r"(b0), "r"(b1));
}

__global__ void zero_agg_kernel() {
    const size_t n4 = (size_t)Bq * Nn * FIL / 4;
    float4* p = (float4*)g_agg;
    for (size_t i = (size_t)blockIdx.x * blockDim.x + threadIdx.x; i < n4;
         i += (size_t)gridDim.x * blockDim.x)
        p[i] = make_float4(0.f, 0.f, 0.f, 0.f);
}

// ---------------- edge kernel smem layout (float words) ----------------
// Bp: [72 k2][96 n] uint32 (bf16x2), XOR-swizzled: idx = k2*96 + (n ^ ((k2&3)*8))
#define S_BPH   0
#define S_BPL   6912
#define S_MS    13824            // 128 x 96 f32
#define S_BM    26112
#define S_GM    26208
#define S_BT    26304
#define S_MEAN  26400            // 128
#define S_RSTD  26528            // 128
#define S_SEB   26656            // 128 int2 = 256 words
#define S_TOTAL 26912
#define E_SMEM_BYTES (S_TOTAL * 4)

__global__ void __launch_bounds__(256, 2) edge_kernel_mma(
    const float* __restrict__ nodes, const float* __restrict__ ef,
    const int*   __restrict__ edges, const float* __restrict__ Wm,
    const float* __restrict__ bm,    const float* __restrict__ gm,
    const float* __restrict__ bt,    float* __restrict__ msg_out)
{
    extern __shared__ float sm[];
    uint32_t* Bh   = (uint32_t*)(sm + S_BPH);
    uint32_t* Bl   = (uint32_t*)(sm + S_BPL);
    float*    Ms   = sm + S_MS;
    float*    bm_s = sm + S_BM;
    float*    gm_s = sm + S_GM;
    float*    bt_s = sm + S_BT;
    float*    mn_s = sm + S_MEAN;
    float*    rs_s = sm + S_RSTD;
    int2*     seb  = (int2*)(sm + S_SEB);

    const int t = threadIdx.x;

    // ---- stage weights: pack (W[2k2][n], W[2k2+1][n]) -> bf16x2 hi/lo ----
    for (int i = t; i < 72 * 96; i += 256) {
        int k2 = i / 96, n = i - k2 * 96;
        float x0 = Wm[(2 * k2) * FIL + n];
        float x1 = Wm[(2 * k2 + 1) * FIL + n];
        uint32_t lo2;
        uint32_t hi2 = split_pair(x0, x1, lo2);
        int idx = k2 * 96 + (n ^ ((k2 & 3) * 8));
        Bh[idx] = hi2;
        Bl[idx] = lo2;
    }
    if (t < FIL) { bm_s[t] = bm[t]; gm_s[t] = gm[t]; bt_s[t] = bt[t]; }
    if (t < 128) seb[t] = ((const int2*)edges)[blockIdx.x * 128 + t];
    __syncthreads();

    // ---- per-thread fragment coordinates ----
    const int lane = t & 31;
    const int w    = t >> 5;
    const int g    = lane >> 2;      // 0..7
    const int q    = lane & 3;       // 0..3
    const int row0 = w * 16 + g;
    const int row1 = row0 + 8;
    const int ge0  = blockIdx.x * 128 + row0;
    const int ge1  = ge0 + 8;
    const int b0   = ge0 / Ee;
    const int b1   = ge1 / Ee;
    const int2 e0  = seb[row0];
    const int2 e1  = seb[row1];

    const float* src0 = nodes + ((size_t)b0 * Nn + e0.x) * Ff;
    const float* dst0 = nodes + ((size_t)b0 * Nn + e0.y) * Ff;
    const float* ef0  = ef + (size_t)ge0 * FEe;
    const float* src1 = nodes + ((size_t)b1 * Nn + e1.x) * Ff;
    const float* dst1 = nodes + ((size_t)b1 * Nn + e1.y) * Ff;
    const float* ef1  = ef + (size_t)ge1 * FEe;

    float c[12][4];
    #pragma unroll
    for (int nt = 0; nt < 12; nt++) { c[nt][0]=0.f; c[nt][1]=0.f; c[nt][2]=0.f; c[nt][3]=0.f; }

    const int nsw = q * 8;  // B swizzle term (k2&3 == q for both b0 and b1 rows)

    // ---- main loop: 9 k-steps of 16 ----
    #pragma unroll
    for (int kt = 0; kt < 9; kt++) {
        const float* p0;
        const float* p1;
        int off;
        if (kt < 4)      { p0 = src0; p1 = src1; off = kt * 16; }
        else if (kt < 8) { p0 = dst0; p1 = dst1; off = (kt - 4) * 16; }
        else             { p0 = ef0;  p1 = ef1;  off = 0; }
        off += 2 * q;

        float2 x00 = *(const float2*)(p0 + off);        // row0, k:k+1
        float2 x02 = *(const float2*)(p0 + off + 8);    // row0, k+8:k+9
        float2 x10 = *(const float2*)(p1 + off);        // row1
        float2 x12 = *(const float2*)(p1 + off + 8);

        uint32_t ah[4], al[4];
        ah[0] = split_pair(x00.x, x00.y, al[0]);
        ah[1] = split_pair(x10.x, x10.y, al[1]);
        ah[2] = split_pair(x02.x, x02.y, al[2]);
        ah[3] = split_pair(x12.x, x12.y, al[3]);

        const int kb = kt * 8;
        // T1 (Ah*Bh) + T2 (Al*Bh): share Bh fragments
        #pragma unroll
        for (int nt = 0; nt < 12; nt++) {
            const int n = nt * 8 + g;
            uint32_t bh0 = Bh[(kb + q) * 96 + (n ^ nsw)];
            uint32_t bh1 = Bh[(kb + 4 + q) * 96 + (n ^ nsw)];
            mma_bf16(c[nt], ah, bh0, bh1);
            mma_bf16(c[nt], al, bh0, bh1);
        }
        // T3 (Ah*Bl)
        #pragma unroll
        for (int nt = 0; nt < 12; nt++) {
            const int n = nt * 8 + g;
            uint32_t bl0 = Bl[(kb + q) * 96 + (n ^ nsw)];
            uint32_t bl1 = Bl[(kb + 4 + q) * 96 + (n ^ nsw)];
            mma_bf16(c[nt], ah, bl0, bl1);
        }
    }

    // ---- bias + relu + LN stats (rows owned by 4-lane quads) ----
    float sum0 = 0.f, sq0 = 0.f, sum1 = 0.f, sq1 = 0.f;
    #pragma unroll
    for (int nt = 0; nt < 12; nt++) {
        const int j = nt * 8 + 2 * q;
        const float bv0 = bm_s[j], bv1 = bm_s[j + 1];
        float v0 = fmaxf(c[nt][0] + bv0, 0.f);
        float v1 = fmaxf(c[nt][1] + bv1, 0.f);
        float v2 = fmaxf(c[nt][2] + bv0, 0.f);
        float v3 = fmaxf(c[nt][3] + bv1, 0.f);
        c[nt][0] = v0; c[nt][1] = v1; c[nt][2] = v2; c[nt][3] = v3;
        sum0 += v0 + v1;  sq0 += v0 * v0 + v1 * v1;
        sum1 += v2 + v3;  sq1 += v2 * v2 + v3 * v3;
    }
    #pragma unroll
    for (int m = 1; m < 4; m <<= 1) {
        sum0 += __shfl_xor_sync(0xffffffffu, sum0, m);
        sq0  += __shfl_xor_sync(0xffffffffu, sq0,  m);
        sum1 += __shfl_xor_sync(0xffffffffu, sum1, m);
        sq1  += __shfl_xor_sync(0xffffffffu, sq1,  m);
    }
    if (q == 0) {
        float mean = sum0 * (1.f / FIL);
        float var  = sq0 * (1.f / FIL) - mean * mean;
        mn_s[row0] = mean; rs_s[row0] = rsqrtf(var + LN_EPS);
        mean = sum1 * (1.f / FIL);
        var  = sq1 * (1.f / FIL) - mean * mean;
        mn_s[row1] = mean; rs_s[row1] = rsqrtf(var + LN_EPS);
    }

    // ---- stash raw relu'd values ----
    #pragma unroll
    for (int nt = 0; nt < 12; nt++) {
        const int j = nt * 8 + 2 * q;
        *(float2*)(Ms + row0 * 96 + j) = make_float2(c[nt][0], c[nt][1]);
        *(float2*)(Ms + row1 * 96 + j) = make_float2(c[nt][2], c[nt][3]);
    }
    __syncthreads();

    // ---- output: LN apply + coalesced store + vector atomics ----
    for (int i = t; i < 128 * 24; i += 256) {
        const int row = i / 24;
        const int c4  = i - row * 24;
        const int j   = c4 * 4;
        const float mean = mn_s[row], rstd = rs_s[row];
        float4 v = *(const float4*)(Ms + row * 96 + j);
        float4 o;
        o.x = (v.x - mean) * rstd * gm_s[j + 0] + bt_s[j + 0];
        o.y = (v.y - mean) * rstd * gm_s[j + 1] + bt_s[j + 1];
        o.z = (v.z - mean) * rstd * gm_s[j + 2] + bt_s[j + 2];
        o.w = (v.w - mean) * rstd * gm_s[j + 3] + bt_s[j + 3];
        const int ge = blockIdx.x * 128 + row;
        const int b  = ge / Ee;
        ((float4*)(msg_out + (size_t)ge * FIL))[c4] = o;
        red4(g_agg + ((size_t)b * Nn + seb[row].y) * FIL + j, o);
    }
}

// ---------------- node kernel (scalar FFMA2, unchanged from R3) ----------------
__device__ __forceinline__ unsigned long long dup2(float x) {
    unsigned long long r; asm("mov.b64 %0, {%1, %1};" : "=l"(r) : "f"(x)); return r;
}
__device__ __forceinline__ void fma2(unsigned long long& d, unsigned long long a,
                                     unsigned long long b) {
    asm("fma.rn.f32x2 %0, %1, %2, %0;" : "+l"(d) : "l"(a), "l"(b));
}
__device__ __forceinline__ void unpack2(unsigned long long v, float& lo, float& hi) {
    asm("mov.b64 {%0, %1}, %2;" : "=f"(lo), "=f"(hi) : "l"(v));
}

#define U_WS   0
#define U_AS   15360
#define U_BM   25600
#define U_GM   25696
#define U_BT   25792
#define U_SMEM_BYTES (25888 * 4)

__global__ void __launch_bounds__(256, 2) node_kernel(
    const float* __restrict__ nodes, const float* __restrict__ Wu,
    const float* __restrict__ bu,    const float* __restrict__ gm,
    const float* __restrict__ bt,    float* __restrict__ upd_out)
{
    extern __shared__ float sm[];
    float* Ws = sm + U_WS;  float* As = sm + U_AS;  float* Ms = sm + U_AS;
    float* bm_s = sm + U_BM; float* gm_s = sm + U_GM; float* bt_s = sm + U_BT;
    const int t = threadIdx.x;

    {
        const float4* w4 = (const float4*)Wu;
        float4* s4 = (float4*)Ws;
        for (int i = t; i < (DU * FIL) / 4; i += 256) s4[i] = w4[i];
        if (t < FIL) { bm_s[t] = bu[t]; gm_s[t] = gm[t]; bt_s[t] = bt[t]; }
    }
    const int ln = t >> 2, sub = t & 3;
    const int gn = blockIdx.x * 64 + ln;
    const int b = gn / Nn, n = gn % Nn;
    {
        const float4* nr = (const float4*)(nodes + ((size_t)b * Nn + n) * Ff);
        #pragma unroll
        for (int ii = 0; ii < 4; ii++) {
            float4 v = nr[sub * 4 + ii];
            int k = sub * 16 + ii * 4;
            As[(k+0)*64+ln]=v.x; As[(k+1)*64+ln]=v.y; As[(k+2)*64+ln]=v.z; As[(k+3)*64+ln]=v.w;
        }
        const float4* ar = (const float4*)(g_agg + ((size_t)b * Nn + n) * FIL);
        #pragma unroll
        for (int ii = 0; ii < 6; ii++) {
            float4 v = ar[sub * 6 + ii];
            int k = Ff + sub * 24 + ii * 4;
            As[(k+0)*64+ln]=v.x; As[(k+1)*64+ln]=v.y; As[(k+2)*64+ln]=v.z; As[(k+3)*64+ln]=v.w;
        }
    }
    __syncthreads();

    const int tx = t & 15, ty = t >> 4;
    const float* Ap = As + ty * 4;
    const float* Wp = Ws + tx * 6;
    unsigned long long acc[4][3];
    #pragma unroll
    for (int i = 0; i < 4; i++) { acc[i][0]=0ULL; acc[i][1]=0ULL; acc[i][2]=0ULL; }

    #pragma unroll 4
    for (int k = 0; k < DU; k++) {
        float4 a = *(const float4*)(Ap + k * 64);
        unsigned long long a0=dup2(a.x), a1=dup2(a.y), a2=dup2(a.z), a3=dup2(a.w);
        const float* wk = Wp + k * FIL;
        unsigned long long w0 = *(const unsigned long long*)(wk + 0);
        unsigned long long w1 = *(const unsigned long long*)(wk + 2);
        unsigned long long w2 = *(const unsigned long long*)(wk + 4);
        fma2(acc[0][0],a0,w0); fma2(acc[0][1],a0,w1); fma2(acc[0][2],a0,w2);
        fma2(acc[1][0],a1,w0); fma2(acc[1][1],a1,w1); fma2(acc[1][2],a1,w2);
        fma2(acc[2][0],a2,w0); fma2(acc[2][1],a2,w1); fma2(acc[2][2],a2,w2);
        fma2(acc[3][0],a3,w0); fma2(acc[3][1],a3,w1); fma2(acc[3][2],a3,w2);
    }

    float r[4][6], s[4], qq[4];
    #pragma unroll
    for (int ei = 0; ei < 4; ei++) {
        s[ei] = 0.f; qq[ei] = 0.f;
        #pragma unroll
        for (int p = 0; p < 3; p++) {
            float lo, hi; unpack2(acc[ei][p], lo, hi);
            const int j = tx * 6 + 2 * p;
            lo = fmaxf(lo + bm_s[j], 0.f);
            hi = fmaxf(hi + bm_s[j + 1], 0.f);
            r[ei][2*p] = lo; r[ei][2*p+1] = hi;
            s[ei] += lo + hi; qq[ei] += lo * lo + hi * hi;
        }
    }
    #pragma unroll
    for (int m = 1; m < 16; m <<= 1)
        #pragma unroll
        for (int ei = 0; ei < 4; ei++) {
            s[ei]  += __shfl_xor_sync(0xffffffffu, s[ei],  m);
            qq[ei] += __shfl_xor_sync(0xffffffffu, qq[ei], m);
        }

    __syncthreads();
    #pragma unroll
    for (int ei = 0; ei < 4; ei++) {
        const float mean = s[ei] * (1.f / FIL);
        const float var  = qq[ei] * (1.f / FIL) - mean * mean;
        const float rstd = rsqrtf(var + LN_EPS);
        const int el = ty * 4 + ei;
        #pragma unroll
        for (int jj = 0; jj < 6; jj++) {
            const int j = tx * 6 + jj;
            Ms[el * FIL + j] = (r[ei][jj] - mean) * rstd * gm_s[j] + bt_s[j];
        }
    }
    __syncthreads();

    float4* uo = (float4*)(upd_out + (size_t)blockIdx.x * 64 * FIL);
    const float4* ms4 = (const float4*)Ms;
    #pragma unroll
    for (int rr = 0; rr < 6; rr++) uo[t + rr * 256] = ms4[t + rr * 256];
}

// ---------------- launch ----------------
extern "C" void kernel_launch(void* const* d_in, const int* in_sizes, int n_in,
                              void* d_out, int out_size) {
    const float* nodes = (const float*)d_in[0];
    const float* ef    = (const float*)d_in[1];
    const int*   edges = (const int*)  d_in[2];
    const float* Wm    = (const float*)d_in[3];
    const float* bm    = (const float*)d_in[4];
    const float* gm_m  = (const float*)d_in[5];
    const float* bt_m  = (const float*)d_in[6];
    const float* Wu    = (const float*)d_in[7];
    const float* bu    = (const float*)d_in[8];
    const float* gm_u  = (const float*)d_in[9];
    const float* bt_u  = (const float*)d_in[10];

    float* out = (float*)d_out;
    float* upd = out;                               // (B, N, FILTERS)
    float* msg = out + (size_t)Bq * Nn * FIL;       // (B, E, FILTERS)

    cudaFuncSetAttribute(edge_kernel_mma, cudaFuncAttributeMaxDynamicSharedMemorySize,
                         E_SMEM_BYTES);
    cudaFuncSetAttribute(node_kernel, cudaFuncAttributeMaxDynamicSharedMemorySize,
                         U_SMEM_BYTES);

    zero_agg_kernel<<<1875, 512>>>();
    edge_kernel_mma<<<(Bq * Ee) / 128, 256, E_SMEM_BYTES>>>(
        nodes, ef, edges, Wm, bm, gm_m, bt_m, msg);
    node_kernel<<<(Bq * Nn) / 64, 256, U_SMEM_BYTES>>>(
        nodes, Wu, bu, gm_u, bt_u, upd);
}

// round 8
// speedup vs baseline: 1.9255x; 1.2113x over previous
#include <cuda_runtime.h>
#include <cstdint>

#define Bq   8
#define Nn   5000
#define Ee   40000
#define Ff   64
#define FEe  16
#define FIL  96
#define DM   144
#define DU   160
#define LN_EPS 1e-3f
#define MSTR 104   // Ms row stride (words) — conflict-free

__device__ __align__(16) float g_agg[(size_t)Bq * Nn * FIL];

// ---------------- helpers ----------------
__device__ __forceinline__ void red4(float* addr, float4 v) {
    asm volatile("red.global.add.v4.f32 [%0], {%1,%2,%3,%4};"
                 :: "l"(addr), "f"(v.x), "f"(v.y), "f"(v.z), "f"(v.w) : "memory");
}
// split (x,y) fp32 pair into bf16x2 hi + bf16x2 lo (lo = residual)
__device__ __forceinline__ uint32_t split_pair(float x, float y, uint32_t& lo2) {
    uint32_t h;
    asm("cvt.rn.bf16x2.f32 %0, %1, %2;" : "=r"(h) : "f"(y), "f"(x));
    float hx = __uint_as_float(h << 16);
    float hy = __uint_as_float(h & 0xffff0000u);
    float rx = x - hx, ry = y - hy;
    asm("cvt.rn.bf16x2.f32 %0, %1, %2;" : "=r"(lo2) : "f"(ry), "f"(rx));
    return h;
}
__device__ __forceinline__ void mma_bf16(float* c, const uint32_t* a,
                                         uint32_t b0, uint32_t b1) {
    asm volatile(
        "mma.sync.aligned.m16n8k16.row.col.f32.bf16.bf16.f32 "
        "{%0,%1,%2,%3}, {%4,%5,%6,%7}, {%8,%9}, {%0,%1,%2,%3};"
        : "+f"(c[0]), "+f"(c[1]), "+f"(c[2]), "+f"(c[3])
        : "r"(a[0]), "r"(a[1]), "r"(a[2]), "r"(a[3]), "r"(b0), "r"(b1));
}
// load one 16-wide k-slab of a row and split
__device__ __forceinline__ void load_split(const float* p, int off,
                                           uint32_t& h0, uint32_t& h2,
                                           uint32_t& l0, uint32_t& l2) {
    float2 x0 = *(const float2*)(p + off);
    float2 x2 = *(const float2*)(p + off + 8);
    h0 = split_pair(x0.x, x0.y, l0);
    h2 = split_pair(x2.x, x2.y, l2);
}

__global__ void zero_agg_kernel() {
    const size_t n4 = (size_t)Bq * Nn * FIL / 4;
    float4* p = (float4*)g_agg;
    for (size_t i = (size_t)blockIdx.x * blockDim.x + threadIdx.x; i < n4;
         i += (size_t)gridDim.x * blockDim.x)
        p[i] = make_float4(0.f, 0.f, 0.f, 0.f);
}

// ================= edge kernel =================
// 128 edges/block, 4 warps; each warp: 32 rows x 96 cols, 9 k-steps, 3 terms.
// B16[slot][n'] : uint4 {bh_k2a, bh_k2b, bl_k2a, bl_k2b}, slot = kt*4+q,
// n' = n ^ (2q)  (bank swizzle). Ms (stride 104) overlays B16 after MMA.
#define ES_B16   0            // 36*96 uint4 = 13824 words (55.3 KB)
#define ES_BM    13824
#define ES_GM    13920
#define ES_BT    14016
#define ES_MEAN  14112        // 128
#define ES_RSTD  14240        // 128
#define ES_SEB   14368        // 128 int2 = 256 words
#define ES_TOTAL 14624
#define E_SMEM_BYTES (ES_TOTAL * 4)

__global__ void __launch_bounds__(128) edge_kernel_mma(
    const float* __restrict__ nodes, const float* __restrict__ ef,
    const int*   __restrict__ edges, const float* __restrict__ Wm,
    const float* __restrict__ bm,    const float* __restrict__ gm,
    const float* __restrict__ bt,    float* __restrict__ msg_out)
{
    extern __shared__ float sm[];
    uint4* B16  = (uint4*)sm;
    float* Ms   = sm;                 // overlay after MMA, stride MSTR
    float* bm_s = sm + ES_BM;
    float* gm_s = sm + ES_GM;
    float* bt_s = sm + ES_BT;
    float* mn_s = sm + ES_MEAN;
    float* rs_s = sm + ES_RSTD;
    int2*  seb  = (int2*)(sm + ES_SEB);

    const int t = threadIdx.x;

    // ---- stage weights as paired hi/lo uint4 ----
    for (int i = t; i < 36 * 96; i += 128) {
        int slot = i / 96, n = i - slot * 96;
        int kt = slot >> 2, q = slot & 3;
        int k2a = kt * 8 + q, k2b = k2a + 4;
        uint32_t la, lb;
        uint32_t ha = split_pair(Wm[(2 * k2a) * FIL + n], Wm[(2 * k2a + 1) * FIL + n], la);
        uint32_t hb = split_pair(Wm[(2 * k2b) * FIL + n], Wm[(2 * k2b + 1) * FIL + n], lb);
        B16[slot * 96 + (n ^ (2 * q))] = make_uint4(ha, hb, la, lb);
    }
    if (t < FIL) { bm_s[t] = bm[t]; gm_s[t] = gm[t]; bt_s[t] = bt[t]; }
    seb[t] = ((const int2*)edges)[blockIdx.x * 128 + t];
    __syncthreads();

    const int lane = t & 31;
    const int w    = t >> 5;
    const int g    = lane >> 2;
    const int q    = lane & 3;
    const int r0 = w * 32 + g, r1 = r0 + 8, r2 = r0 + 16, r3 = r0 + 24;

    const int ge0 = blockIdx.x * 128 + r0;
    const int ge1 = ge0 + 8, ge2 = ge0 + 16, ge3 = ge0 + 24;
    const int b0 = ge0 / Ee, b1 = ge1 / Ee, b2 = ge2 / Ee, b3 = ge3 / Ee;
    const int2 e0 = seb[r0], e1 = seb[r1], e2 = seb[r2], e3 = seb[r3];

    const float* s0 = nodes + ((size_t)b0 * Nn + e0.x) * Ff;
    const float* s1 = nodes + ((size_t)b1 * Nn + e1.x) * Ff;
    const float* s2 = nodes + ((size_t)b2 * Nn + e2.x) * Ff;
    const float* s3 = nodes + ((size_t)b3 * Nn + e3.x) * Ff;
    const float* d0 = nodes + ((size_t)b0 * Nn + e0.y) * Ff;
    const float* d1 = nodes + ((size_t)b1 * Nn + e1.y) * Ff;
    const float* d2 = nodes + ((size_t)b2 * Nn + e2.y) * Ff;
    const float* d3 = nodes + ((size_t)b3 * Nn + e3.y) * Ff;
    const float* f0 = ef + (size_t)ge0 * FEe;
    const float* f1 = ef + (size_t)ge1 * FEe;
    const float* f2 = ef + (size_t)ge2 * FEe;
    const float* f3 = ef + (size_t)ge3 * FEe;

    float c0[12][4], c1[12][4];
    #pragma unroll
    for (int nt = 0; nt < 12; nt++) {
        c0[nt][0]=0.f; c0[nt][1]=0.f; c0[nt][2]=0.f; c0[nt][3]=0.f;
        c1[nt][0]=0.f; c1[nt][1]=0.f; c1[nt][2]=0.f; c1[nt][3]=0.f;
    }

    const int gsw = g ^ (2 * q);

    #pragma unroll
    for (int kt = 0; kt < 9; kt++) {
        const float *pa, *pb, *pc, *pd;
        int off;
        if (kt < 4)      { pa=s0; pb=s1; pc=s2; pd=s3; off = kt * 16; }
        else if (kt < 8) { pa=d0; pb=d1; pc=d2; pd=d3; off = (kt - 4) * 16; }
        else             { pa=f0; pb=f1; pc=f2; pd=f3; off = 0; }
        off += 2 * q;

        uint32_t ah0[4], al0[4], ah1[4], al1[4];
        load_split(pa, off, ah0[0], ah0[2], al0[0], al0[2]);
        load_split(pb, off, ah0[1], ah0[3], al0[1], al0[3]);
        load_split(pc, off, ah1[0], ah1[2], al1[0], al1[2]);
        load_split(pd, off, ah1[1], ah1[3], al1[1], al1[3]);

        const uint4* Bp = B16 + (kt * 4 + q) * 96 + gsw;
        #pragma unroll
        for (int nt = 0; nt < 12; nt++) {
            uint4 Bv = Bp[nt * 8];
            mma_bf16(c0[nt], ah0, Bv.x, Bv.y);
            mma_bf16(c0[nt], al0, Bv.x, Bv.y);
            mma_bf16(c0[nt], ah0, Bv.z, Bv.w);
            mma_bf16(c1[nt], ah1, Bv.x, Bv.y);
            mma_bf16(c1[nt], al1, Bv.x, Bv.y);
            mma_bf16(c1[nt], ah1, Bv.z, Bv.w);
        }
    }

    // ---- bias + relu + LN stats (quad owns rows) ----
    float sums[4] = {0.f, 0.f, 0.f, 0.f}, sqs[4] = {0.f, 0.f, 0.f, 0.f};
    #pragma unroll
    for (int nt = 0; nt < 12; nt++) {
        const int j = nt * 8 + 2 * q;
        const float bv0 = bm_s[j], bv1 = bm_s[j + 1];
        float v;
        v = fmaxf(c0[nt][0] + bv0, 0.f); c0[nt][0] = v; sums[0] += v; sqs[0] += v * v;
        v = fmaxf(c0[nt][1] + bv1, 0.f); c0[nt][1] = v; sums[0] += v; sqs[0] += v * v;
        v = fmaxf(c0[nt][2] + bv0, 0.f); c0[nt][2] = v; sums[1] += v; sqs[1] += v * v;
        v = fmaxf(c0[nt][3] + bv1, 0.f); c0[nt][3] = v; sums[1] += v; sqs[1] += v * v;
        v = fmaxf(c1[nt][0] + bv0, 0.f); c1[nt][0] = v; sums[2] += v; sqs[2] += v * v;
        v = fmaxf(c1[nt][1] + bv1, 0.f); c1[nt][1] = v; sums[2] += v; sqs[2] += v * v;
        v = fmaxf(c1[nt][2] + bv0, 0.f); c1[nt][2] = v; sums[3] += v; sqs[3] += v * v;
        v = fmaxf(c1[nt][3] + bv1, 0.f); c1[nt][3] = v; sums[3] += v; sqs[3] += v * v;
    }
    #pragma unroll
    for (int m = 1; m < 4; m <<= 1) {
        #pragma unroll
        for (int rr = 0; rr < 4; rr++) {
            sums[rr] += __shfl_xor_sync(0xffffffffu, sums[rr], m);
            sqs[rr]  += __shfl_xor_sync(0xffffffffu, sqs[rr],  m);
        }
    }
    if (q == 0) {
        const int rws[4] = {r0, r1, r2, r3};
        #pragma unroll
        for (int rr = 0; rr < 4; rr++) {
            float mean = sums[rr] * (1.f / FIL);
            float var  = sqs[rr] * (1.f / FIL) - mean * mean;
            mn_s[rws[rr]] = mean;
            rs_s[rws[rr]] = rsqrtf(var + LN_EPS);
        }
    }
    __syncthreads();   // all warps done reading B16 -> safe to overlay Ms

    #pragma unroll
    for (int nt = 0; nt < 12; nt++) {
        const int j = nt * 8 + 2 * q;
        *(float2*)(Ms + r0 * MSTR + j) = make_float2(c0[nt][0], c0[nt][1]);
        *(float2*)(Ms + r1 * MSTR + j) = make_float2(c0[nt][2], c0[nt][3]);
        *(float2*)(Ms + r2 * MSTR + j) = make_float2(c1[nt][0], c1[nt][1]);
        *(float2*)(Ms + r3 * MSTR + j) = make_float2(c1[nt][2], c1[nt][3]);
    }
    __syncthreads();

    // ---- output: LN apply + coalesced store + vector atomics ----
    for (int i = t; i < 128 * 24; i += 128) {
        const int row = i / 24;
        const int c4  = i - row * 24;
        const int j   = c4 * 4;
        const float mean = mn_s[row], rstd = rs_s[row];
        float4 v = *(const float4*)(Ms + row * MSTR + j);
        float4 o;
        o.x = (v.x - mean) * rstd * gm_s[j + 0] + bt_s[j + 0];
        o.y = (v.y - mean) * rstd * gm_s[j + 1] + bt_s[j + 1];
        o.z = (v.z - mean) * rstd * gm_s[j + 2] + bt_s[j + 2];
        o.w = (v.w - mean) * rstd * gm_s[j + 3] + bt_s[j + 3];
        const int ge = blockIdx.x * 128 + row;
        const int b  = ge / Ee;
        ((float4*)(msg_out + (size_t)ge * FIL))[c4] = o;
        red4(g_agg + ((size_t)b * Nn + seb[row].y) * FIL + j, o);
    }
}

// ================= node kernel (same scheme, K=160, 10 k-steps) =================
#define NS_B16   0            // 40*96 uint4 = 15360 words (61.4 KB)
#define NS_BM    15360
#define NS_GM    15456
#define NS_BT    15552
#define NS_MEAN  15648
#define NS_RSTD  15776
#define NS_TOTAL 15904
#define N_SMEM_BYTES (NS_TOTAL * 4)

__global__ void __launch_bounds__(128) node_kernel_mma(
    const float* __restrict__ nodes, const float* __restrict__ Wu,
    const float* __restrict__ bu,    const float* __restrict__ gm,
    const float* __restrict__ bt,    float* __restrict__ upd_out)
{
    extern __shared__ float sm[];
    uint4* B16  = (uint4*)sm;
    float* Ms   = sm;
    float* bm_s = sm + NS_BM;
    float* gm_s = sm + NS_GM;
    float* bt_s = sm + NS_BT;
    float* mn_s = sm + NS_MEAN;
    float* rs_s = sm + NS_RSTD;

    const int t = threadIdx.x;

    for (int i = t; i < 40 * 96; i += 128) {
        int slot = i / 96, n = i - slot * 96;
        int kt = slot >> 2, q = slot & 3;
        int k2a = kt * 8 + q, k2b = k2a + 4;
        uint32_t la, lb;
        uint32_t ha = split_pair(Wu[(2 * k2a) * FIL + n], Wu[(2 * k2a + 1) * FIL + n], la);
        uint32_t hb = split_pair(Wu[(2 * k2b) * FIL + n], Wu[(2 * k2b + 1) * FIL + n], lb);
        B16[slot * 96 + (n ^ (2 * q))] = make_uint4(ha, hb, la, lb);
    }
    if (t < FIL) { bm_s[t] = bu[t]; gm_s[t] = gm[t]; bt_s[t] = bt[t]; }
    __syncthreads();

    const int lane = t & 31;
    const int w    = t >> 5;
    const int g    = lane >> 2;
    const int q    = lane & 3;
    const int r0 = w * 32 + g, r1 = r0 + 8, r2 = r0 + 16, r3 = r0 + 24;

    const int NT = Bq * Nn;
    int gn[4] = {blockIdx.x * 128 + r0, blockIdx.x * 128 + r1,
                 blockIdx.x * 128 + r2, blockIdx.x * 128 + r3};
    const float* np[4];
    const float* ap[4];
    #pragma unroll
    for (int rr = 0; rr < 4; rr++) {
        int gc = gn[rr] < NT ? gn[rr] : NT - 1;
        int b = gc / Nn, n = gc - b * Nn;
        np[rr] = nodes + ((size_t)b * Nn + n) * Ff;
        ap[rr] = g_agg + ((size_t)b * Nn + n) * FIL;
    }

    float c0[12][4], c1[12][4];
    #pragma unroll
    for (int nt = 0; nt < 12; nt++) {
        c0[nt][0]=0.f; c0[nt][1]=0.f; c0[nt][2]=0.f; c0[nt][3]=0.f;
        c1[nt][0]=0.f; c1[nt][1]=0.f; c1[nt][2]=0.f; c1[nt][3]=0.f;
    }
    const int gsw = g ^ (2 * q);

    #pragma unroll
    for (int kt = 0; kt < 10; kt++) {
        const float *pa, *pb, *pc, *pd;
        int off;
        if (kt < 4) { pa=np[0]; pb=np[1]; pc=np[2]; pd=np[3]; off = kt * 16; }
        else        { pa=ap[0]; pb=ap[1]; pc=ap[2]; pd=ap[3]; off = (kt - 4) * 16; }
        off += 2 * q;

        uint32_t ah0[4], al0[4], ah1[4], al1[4];
        load_split(pa, off, ah0[0], ah0[2], al0[0], al0[2]);
        load_split(pb, off, ah0[1], ah0[3], al0[1], al0[3]);
        load_split(pc, off, ah1[0], ah1[2], al1[0], al1[2]);
        load_split(pd, off, ah1[1], ah1[3], al1[1], al1[3]);

        const uint4* Bp = B16 + (kt * 4 + q) * 96 + gsw;
        #pragma unroll
        for (int nt = 0; nt < 12; nt++) {
            uint4 Bv = Bp[nt * 8];
            mma_bf16(c0[nt], ah0, Bv.x, Bv.y);
            mma_bf16(c0[nt], al0, Bv.x, Bv.y);
            mma_bf16(c0[nt], ah0, Bv.z, Bv.w);
            mma_bf16(c1[nt], ah1, Bv.x, Bv.y);
            mma_bf16(c1[nt], al1, Bv.x, Bv.y);
            mma_bf16(c1[nt], ah1, Bv.z, Bv.w);
        }
    }

    float sums[4] = {0.f, 0.f, 0.f, 0.f}, sqs[4] = {0.f, 0.f, 0.f, 0.f};
    #pragma unroll
    for (int nt = 0; nt < 12; nt++) {
        const int j = nt * 8 + 2 * q;
        const float bv0 = bm_s[j], bv1 = bm_s[j + 1];
        float v;
        v = fmaxf(c0[nt][0] + bv0, 0.f); c0[nt][0] = v; sums[0] += v; sqs[0] += v * v;
        v = fmaxf(c0[nt][1] + bv1, 0.f); c0[nt][1] = v; sums[0] += v; sqs[0] += v * v;
        v = fmaxf(c0[nt][2] + bv0, 0.f); c0[nt][2] = v; sums[1] += v; sqs[1] += v * v;
        v = fmaxf(c0[nt][3] + bv1, 0.f); c0[nt][3] = v; sums[1] += v; sqs[1] += v * v;
        v = fmaxf(c1[nt][0] + bv0, 0.f); c1[nt][0] = v; sums[2] += v; sqs[2] += v * v;
        v = fmaxf(c1[nt][1] + bv1, 0.f); c1[nt][1] = v; sums[2] += v; sqs[2] += v * v;
        v = fmaxf(c1[nt][2] + bv0, 0.f); c1[nt][2] = v; sums[3] += v; sqs[3] += v * v;
        v = fmaxf(c1[nt][3] + bv1, 0.f); c1[nt][3] = v; sums[3] += v; sqs[3] += v * v;
    }
    #pragma unroll
    for (int m = 1; m < 4; m <<= 1) {
        #pragma unroll
        for (int rr = 0; rr < 4; rr++) {
            sums[rr] += __shfl_xor_sync(0xffffffffu, sums[rr], m);
            sqs[rr]  += __shfl_xor_sync(0xffffffffu, sqs[rr],  m);
        }
    }
    if (q == 0) {
        const int rws[4] = {r0, r1, r2, r3};
        #pragma unroll
        for (int rr = 0; rr < 4; rr++) {
            float mean = sums[rr] * (1.f / FIL);
            float var  = sqs[rr] * (1.f / FIL) - mean * mean;
            mn_s[rws[rr]] = mean;
            rs_s[rws[rr]] = rsqrtf(var + LN_EPS);
        }
    }
    __syncthreads();

    #pragma unroll
    for (int nt = 0; nt < 12; nt++) {
        const int j = nt * 8 + 2 * q;
        *(float2*)(Ms + r0 * MSTR + j) = make_float2(c0[nt][0], c0[nt][1]);
        *(float2*)(Ms + r1 * MSTR + j) = make_float2(c0[nt][2], c0[nt][3]);
        *(float2*)(Ms + r2 * MSTR + j) = make_float2(c1[nt][0], c1[nt][1]);
        *(float2*)(Ms + r3 * MSTR + j) = make_float2(c1[nt][2], c1[nt][3]);
    }
    __syncthreads();

    for (int i = t; i < 128 * 24; i += 128) {
        const int row = i / 24;
        const int c4  = i - row * 24;
        const int j   = c4 * 4;
        const int ge  = blockIdx.x * 128 + row;
        if (ge >= NT) continue;
        const float mean = mn_s[row], rstd = rs_s[row];
        float4 v = *(const float4*)(Ms + row * MSTR + j);
        float4 o;
        o.x = (v.x - mean) * rstd * gm_s[j + 0] + bt_s[j + 0];
        o.y = (v.y - mean) * rstd * gm_s[j + 1] + bt_s[j + 1];
        o.z = (v.z - mean) * rstd * gm_s[j + 2] + bt_s[j + 2];
        o.w = (v.w - mean) * rstd * gm_s[j + 3] + bt_s[j + 3];
        ((float4*)(upd_out + (size_t)ge * FIL))[c4] = o;
    }
}

// ---------------- launch ----------------
extern "C" void kernel_launch(void* const* d_in, const int* in_sizes, int n_in,
                              void* d_out, int out_size) {
    const float* nodes = (const float*)d_in[0];
    const float* ef    = (const float*)d_in[1];
    const int*   edges = (const int*)  d_in[2];
    const float* Wm    = (const float*)d_in[3];
    const float* bm    = (const float*)d_in[4];
    const float* gm_m  = (const float*)d_in[5];
    const float* bt_m  = (const float*)d_in[6];
    const float* Wu    = (const float*)d_in[7];
    const float* bu    = (const float*)d_in[8];
    const float* gm_u  = (const float*)d_in[9];
    const float* bt_u  = (const float*)d_in[10];

    float* out = (float*)d_out;
    float* upd = out;                               // (B, N, FILTERS)
    float* msg = out + (size_t)Bq * Nn * FIL;       // (B, E, FILTERS)

    cudaFuncSetAttribute(edge_kernel_mma, cudaFuncAttributeMaxDynamicSharedMemorySize,
                         E_SMEM_BYTES);
    cudaFuncSetAttribute(node_kernel_mma, cudaFuncAttributeMaxDynamicSharedMemorySize,
                         N_SMEM_BYTES);

    zero_agg_kernel<<<1875, 512>>>();
    edge_kernel_mma<<<(Bq * Ee) / 128, 128, E_SMEM_BYTES>>>(
        nodes, ef, edges, Wm, bm, gm_m, bt_m, msg);
    node_kernel_mma<<<(Bq * Nn + 127) / 128, 128, N_SMEM_BYTES>>>(
        nodes, Wu, bu, gm_u, bt_u, upd);
}